// round 1
// baseline (speedup 1.0000x reference)
#include <cuda_runtime.h>
#include <math.h>

#define Bsz 4
#define Tsz 2048
#define DMx 1024
#define Hh  16
#define Dd  64
#define INNERx 1024
#define ROWS (Bsz*Tsz)   // 8192

// ---------------- scratch (static device allocations; no cudaMalloc allowed) ----
__device__ float g_Q[ROWS*INNERx];
__device__ float g_K[ROWS*INNERx];
__device__ float g_V[ROWS*INNERx];
__device__ float g_Y[ROWS*INNERx];
__device__ float g_alpha[ROWS*Hh];
__device__ float g_beta[ROWS*Hh];

// ---------------- packed f32x2 helpers (FFMA2: 2x fp32 throughput on sm_103a) ---
__device__ __forceinline__ unsigned long long pack_dup(float a){
    unsigned long long r; unsigned int u = __float_as_uint(a);
    asm("mov.b64 %0, {%1, %1};" : "=l"(r) : "r"(u));
    return r;
}
__device__ __forceinline__ void ffma2(unsigned long long& d, unsigned long long a,
                                      unsigned long long b){
    asm("fma.rn.f32x2 %0, %1, %2, %3;" : "=l"(d) : "l"(a), "l"(b), "l"(d));
}

// ---------------- SGEMM: C[M,N] = A[M,K] @ B[K,N], all row-major fp32 -----------
// 128x128 block tile, BK=8, 256 threads, 8x8 microtile via 32 FFMA2 per kk.
// M,N,K all multiples of 128 here -> no bounds checks.
__global__ __launch_bounds__(256)
void sgemm128(const float* __restrict__ A, const float* __restrict__ B,
              float* __restrict__ C, int M, int N, int K){
    __shared__ float As[8][128];
    __shared__ float Bs[8][128];
    const int tid  = threadIdx.x;
    const int bm   = blockIdx.y * 128, bn = blockIdx.x * 128;
    const int arow = tid >> 1,  acol = (tid & 1) << 2;   // 128 rows x 8 cols of A
    const int brow = tid >> 5,  bcol = (tid & 31) << 2;  // 8 rows x 128 cols of B
    const int tr   = (tid >> 4) << 3, tc = (tid & 15) << 3;

    unsigned long long acc[8][4];
    #pragma unroll
    for (int i = 0; i < 8; i++)
        #pragma unroll
        for (int j = 0; j < 4; j++) acc[i][j] = 0ull;

    const float* Ap = A + (size_t)(bm + arow) * K + acol;
    const float* Bp = B + (size_t)brow * N + bn + bcol;

    for (int k0 = 0; k0 < K; k0 += 8){
        float4 av = *(const float4*)Ap;
        float4 bv = *(const float4*)Bp;
        As[acol+0][arow] = av.x;
        As[acol+1][arow] = av.y;
        As[acol+2][arow] = av.z;
        As[acol+3][arow] = av.w;
        *(float4*)&Bs[brow][bcol] = bv;
        __syncthreads();
        #pragma unroll
        for (int kk = 0; kk < 8; kk++){
            unsigned long long bfrag[4];
            const unsigned long long* bp = (const unsigned long long*)&Bs[kk][tc];
            #pragma unroll
            for (int j = 0; j < 4; j++) bfrag[j] = bp[j];
            float af[8];
            #pragma unroll
            for (int i = 0; i < 8; i++) af[i] = As[kk][tr + i];
            #pragma unroll
            for (int i = 0; i < 8; i++){
                unsigned long long a2 = pack_dup(af[i]);
                #pragma unroll
                for (int j = 0; j < 4; j++) ffma2(acc[i][j], a2, bfrag[j]);
            }
        }
        __syncthreads();
        Ap += 8; Bp += (size_t)8 * N;
    }
    #pragma unroll
    for (int i = 0; i < 8; i++){
        float2 o0 = *reinterpret_cast<float2*>(&acc[i][0]);
        float2 o1 = *reinterpret_cast<float2*>(&acc[i][1]);
        float2 o2 = *reinterpret_cast<float2*>(&acc[i][2]);
        float2 o3 = *reinterpret_cast<float2*>(&acc[i][3]);
        float* cr = C + (size_t)(bm + tr + i) * N + bn + tc;
        *(float4*)(cr)     = make_float4(o0.x, o0.y, o1.x, o1.y);
        *(float4*)(cr + 4) = make_float4(o2.x, o2.y, o3.x, o3.y);
    }
}

// ---------------- alpha/beta gate kernel: sigmoid(x @ Wa + ba), (x @ Wb + bb) ---
__global__ __launch_bounds__(128)
void ab_kernel(const float* __restrict__ x,
               const float* __restrict__ Wa, const float* __restrict__ ba,
               const float* __restrict__ Wb, const float* __restrict__ bb,
               float* __restrict__ alpha, float* __restrict__ beta){
    const int row = blockIdx.x;           // 0..8191
    __shared__ float xs[DMx];
    const int tid = threadIdx.x;          // 128
    #pragma unroll
    for (int d = tid; d < DMx; d += 128) xs[d] = x[(size_t)row * DMx + d];
    __syncthreads();
    const int task = tid >> 2;            // 0..31 : 16 alpha cols + 16 beta cols
    const int sub  = tid & 3;
    const int h    = task & 15;
    const float* W = (task < 16) ? Wa : Wb;
    float s = 0.f;
    for (int d = sub; d < DMx; d += 4) s = fmaf(xs[d], W[d * Hh + h], s);
    s += __shfl_xor_sync(0xffffffffu, s, 1);
    s += __shfl_xor_sync(0xffffffffu, s, 2);
    if (sub == 0){
        float bias = (task < 16) ? ba[h] : bb[h];
        float z = s + bias;
        float sig = 1.f / (1.f + expf(-z));
        if (task < 16) alpha[(size_t)row * Hh + h] = sig;
        else           beta [(size_t)row * Hh + h] = sig;
    }
}

// ---------------- K row L2-normalize: rows of length 64, clamp norm to 1e-12 ---
__global__ __launch_bounds__(256)
void knorm_kernel(float* __restrict__ K){
    const int warp = (blockIdx.x * blockDim.x + threadIdx.x) >> 5; // 0..131071
    const int lane = threadIdx.x & 31;
    float* row = K + (size_t)warp * 64;
    float a = row[lane], b = row[lane + 32];
    float ss = a * a + b * b;
    #pragma unroll
    for (int o = 16; o; o >>= 1) ss += __shfl_xor_sync(0xffffffffu, ss, o);
    float inv = 1.f / fmaxf(sqrtf(ss), 1e-12f);
    row[lane] = a * inv;
    row[lane + 32] = b * inv;
}

// ---------------- sequential recurrence: one CTA per (b,h) ----------------------
// thread (i,c): i=tid>>2 in [0,64) row of S, c=tid&3 column quarter (16 cols).
// Per step: S[i,:] = a*S[i,:] + (b*v_i)*k[:] ; y_i = dot(S[i,:], q[:]).
// Double-buffered smem for q/k/v/a/b with register prefetch of step t+1.
__global__ __launch_bounds__(256)
void scan_kernel(const float* __restrict__ Q, const float* __restrict__ K,
                 const float* __restrict__ V,
                 const float* __restrict__ alpha, const float* __restrict__ beta,
                 const float* __restrict__ state0,
                 float* __restrict__ y, float* __restrict__ stateOut){
    const int bh = blockIdx.x;           // 0..63
    const int b  = bh >> 4, h = bh & 15;
    const int tid = threadIdx.x;         // 256
    const int i = tid >> 2, c = tid & 3;

    __shared__ float sq[2][64], sk[2][64], sv[2][64], sab[2][2];

    float S[16];
    const float* s0 = state0 + (((size_t)(b * Hh + h)) * 64 + i) * 64 + c * 16;
    #pragma unroll
    for (int j = 0; j < 16; j++) S[j] = s0[j];

    const size_t base = ((size_t)b * Tsz) * INNERx + (size_t)h * 64; // Q/K/V/y (B,T,H,D)
    const int abbase  = (b * Tsz) * Hh + h;

    // initial load (t = 0) into buffer 0
    if      (tid < 64)   sq[0][tid]       = Q[base + tid];
    else if (tid < 128)  sk[0][tid - 64]  = K[base + tid - 64];
    else if (tid < 192)  sv[0][tid - 128] = V[base + tid - 128];
    else if (tid == 192) sab[0][0] = alpha[abbase];
    else if (tid == 193) sab[0][1] = beta[abbase];
    __syncthreads();

    for (int t = 0; t < Tsz; t++){
        const int cur = t & 1, nxt = cur ^ 1;
        // prefetch t+1 into a register (overlaps with compute below)
        float pf = 0.f;
        if (t + 1 < Tsz){
            size_t off = base + (size_t)(t + 1) * INNERx;
            if      (tid < 64)   pf = Q[off + tid];
            else if (tid < 128)  pf = K[off + tid - 64];
            else if (tid < 192)  pf = V[off + tid - 128];
            else if (tid == 192) pf = alpha[abbase + (t + 1) * Hh];
            else if (tid == 193) pf = beta [abbase + (t + 1) * Hh];
        }
        const float a  = sab[cur][0];
        const float bg = sab[cur][1];
        const float bv = bg * sv[cur][i];
        const float* kc = &sk[cur][c * 16];
        const float* qc = &sq[cur][c * 16];
        float acc = 0.f;
        #pragma unroll
        for (int j = 0; j < 16; j++){
            S[j] = fmaf(bv, kc[j], a * S[j]);
            acc  = fmaf(S[j], qc[j], acc);
        }
        acc += __shfl_xor_sync(0xffffffffu, acc, 1);
        acc += __shfl_xor_sync(0xffffffffu, acc, 2);
        if (c == 0) y[base + (size_t)t * INNERx + i] = acc;
        __syncthreads();
        if (t + 1 < Tsz){
            if      (tid < 64)   sq[nxt][tid]       = pf;
            else if (tid < 128)  sk[nxt][tid - 64]  = pf;
            else if (tid < 192)  sv[nxt][tid - 128] = pf;
            else if (tid == 192) sab[nxt][0] = pf;
            else if (tid == 193) sab[nxt][1] = pf;
        }
        __syncthreads();
    }
    float* so = stateOut + (((size_t)(b * Hh + h)) * 64 + i) * 64 + c * 16;
    #pragma unroll
    for (int j = 0; j < 16; j++) so[j] = S[j];
}

// ---------------- launcher ------------------------------------------------------
extern "C" void kernel_launch(void* const* d_in, const int* in_sizes, int n_in,
                              void* d_out, int out_size){
    const float* x     = (const float*)d_in[0];
    const float* state = (const float*)d_in[1];
    const float* Wq    = (const float*)d_in[2];
    const float* Wk    = (const float*)d_in[3];
    const float* Wv    = (const float*)d_in[4];
    const float* Wa    = (const float*)d_in[5];
    const float* ba    = (const float*)d_in[6];
    const float* Wb    = (const float*)d_in[7];
    const float* bb    = (const float*)d_in[8];
    const float* Wo    = (const float*)d_in[9];

    float* out      = (float*)d_out;                       // (B,T,DM)
    float* stateOut = out + (size_t)ROWS * DMx;            // (B,H,D,D)

    float *Q, *K, *V, *Y, *al, *be;
    cudaGetSymbolAddress((void**)&Q,  g_Q);
    cudaGetSymbolAddress((void**)&K,  g_K);
    cudaGetSymbolAddress((void**)&V,  g_V);
    cudaGetSymbolAddress((void**)&Y,  g_Y);
    cudaGetSymbolAddress((void**)&al, g_alpha);
    cudaGetSymbolAddress((void**)&be, g_beta);

    dim3 gqkv(INNERx / 128, ROWS / 128);   // (8, 64)
    sgemm128<<<gqkv, 256>>>(x, Wq, Q, ROWS, INNERx, DMx);
    sgemm128<<<gqkv, 256>>>(x, Wk, K, ROWS, INNERx, DMx);
    sgemm128<<<gqkv, 256>>>(x, Wv, V, ROWS, INNERx, DMx);
    ab_kernel<<<ROWS, 128>>>(x, Wa, ba, Wb, bb, al, be);
    knorm_kernel<<<(ROWS * Hh) / 8, 256>>>(K);             // 131072 warps
    scan_kernel<<<Bsz * Hh, 256>>>(Q, K, V, al, be, state, Y, stateOut);
    dim3 gout(DMx / 128, ROWS / 128);
    sgemm128<<<gout, 256>>>(Y, Wo, out, ROWS, DMx, INNERx);
}

// round 2
// speedup vs baseline: 1.8031x; 1.8031x over previous
#include <cuda_runtime.h>
#include <math.h>

#define Bsz 4
#define Tsz 2048
#define DMx 1024
#define Hh  16
#define Dd  64
#define INNERx 1024
#define ROWS (Bsz*Tsz)   // 8192
#define CH 64            // chunk length
#define NCH (Tsz/CH)     // 32 chunks
#define BH (Bsz*Hh)      // 64

typedef unsigned long long ull;

// ---------------- scratch ----------------
__device__ float g_Q[ROWS*INNERx];
__device__ float g_K[ROWS*INNERx];
__device__ float g_V[ROWS*INNERx];
__device__ float g_Y[ROWS*INNERx];
__device__ float g_alpha[ROWS*Hh];
__device__ float g_beta[ROWS*Hh];
__device__ float g_U[BH*NCH*Dd*Dd];
__device__ float g_Sc[BH*NCH*Dd*Dd];
__device__ float g_G[BH*NCH];
__device__ float g_gt[BH*Tsz];

// ---------------- packed f32x2 helpers ----------------
__device__ __forceinline__ ull pack_dup(float a){
    ull r; unsigned int u = __float_as_uint(a);
    asm("mov.b64 %0, {%1, %1};" : "=l"(r) : "r"(u));
    return r;
}
__device__ __forceinline__ ull pack2(float x, float y){
    ull r; asm("mov.b64 %0, {%1, %2};" : "=l"(r) : "f"(x), "f"(y));
    return r;
}
__device__ __forceinline__ void ffma2(ull& d, ull a, ull b){
    asm("fma.rn.f32x2 %0, %1, %2, %3;" : "=l"(d) : "l"(a), "l"(b), "l"(d));
}

// ---------------- SGEMM: C = A @ B, row-major fp32, double-buffered BK=16 ------
__global__ __launch_bounds__(256, 2)
void sgemm_db(const float* __restrict__ A, const float* __restrict__ B,
              float* __restrict__ C, int M, int N, int K){
    __shared__ float As[2][16][128];
    __shared__ float Bs[2][16][128];
    const int tid = threadIdx.x;
    const int bm = blockIdx.y * 128, bn = blockIdx.x * 128;
    const int arow = tid >> 1, acol = (tid & 1) << 3;
    const int brow = tid >> 4, bcol = (tid & 15) << 2;
    const int tr = (tid >> 4) << 3, tc = (tid & 15) << 3;

    ull acc[8][4];
    #pragma unroll
    for (int i = 0; i < 8; i++)
        #pragma unroll
        for (int j = 0; j < 4; j++) acc[i][j] = 0ull;

    const float* Ap = A + (size_t)(bm + arow) * K + acol;
    const float* Bp = B + (size_t)brow * N + bn + bcol;

    {   // stage 0
        float4 a0 = *(const float4*)(Ap);
        float4 a1 = *(const float4*)(Ap + 4);
        float4 b0 = *(const float4*)(Bp);
        float4 b1 = *(const float4*)(Bp + 64);
        As[0][acol+0][arow]=a0.x; As[0][acol+1][arow]=a0.y;
        As[0][acol+2][arow]=a0.z; As[0][acol+3][arow]=a0.w;
        As[0][acol+4][arow]=a1.x; As[0][acol+5][arow]=a1.y;
        As[0][acol+6][arow]=a1.z; As[0][acol+7][arow]=a1.w;
        *(float4*)&Bs[0][brow][bcol]      = b0;
        *(float4*)&Bs[0][brow][bcol + 64] = b1;
    }
    __syncthreads();
    int buf = 0;
    const int NT = K >> 4;
    for (int kt = 0; kt < NT; kt++){
        float4 pa0, pa1, pb0, pb1;
        const bool more = (kt + 1 < NT);
        if (more){
            const float* Ap2 = Ap + (kt + 1) * 16;
            const float* Bp2 = Bp + (size_t)(kt + 1) * 16 * N;
            pa0 = *(const float4*)(Ap2);
            pa1 = *(const float4*)(Ap2 + 4);
            pb0 = *(const float4*)(Bp2);
            pb1 = *(const float4*)(Bp2 + 64);
        }
        #pragma unroll
        for (int kk = 0; kk < 16; kk++){
            float4 bv0 = *(const float4*)&Bs[buf][kk][tc];
            float4 bv1 = *(const float4*)&Bs[buf][kk][tc + 4];
            ull bf[4];
            bf[0] = pack2(bv0.x, bv0.y);
            bf[1] = pack2(bv0.z, bv0.w);
            bf[2] = pack2(bv1.x, bv1.y);
            bf[3] = pack2(bv1.z, bv1.w);
            float4 av0 = *(const float4*)&As[buf][kk][tr];
            float4 av1 = *(const float4*)&As[buf][kk][tr + 4];
            float af[8] = {av0.x, av0.y, av0.z, av0.w, av1.x, av1.y, av1.z, av1.w};
            #pragma unroll
            for (int i = 0; i < 8; i++){
                ull a2 = pack_dup(af[i]);
                #pragma unroll
                for (int j = 0; j < 4; j++) ffma2(acc[i][j], a2, bf[j]);
            }
        }
        if (more){
            const int nb = buf ^ 1;
            As[nb][acol+0][arow]=pa0.x; As[nb][acol+1][arow]=pa0.y;
            As[nb][acol+2][arow]=pa0.z; As[nb][acol+3][arow]=pa0.w;
            As[nb][acol+4][arow]=pa1.x; As[nb][acol+5][arow]=pa1.y;
            As[nb][acol+6][arow]=pa1.z; As[nb][acol+7][arow]=pa1.w;
            *(float4*)&Bs[nb][brow][bcol]      = pb0;
            *(float4*)&Bs[nb][brow][bcol + 64] = pb1;
            __syncthreads();
            buf = nb;
        }
    }
    #pragma unroll
    for (int i = 0; i < 8; i++){
        float2 o0 = *reinterpret_cast<float2*>(&acc[i][0]);
        float2 o1 = *reinterpret_cast<float2*>(&acc[i][1]);
        float2 o2 = *reinterpret_cast<float2*>(&acc[i][2]);
        float2 o3 = *reinterpret_cast<float2*>(&acc[i][3]);
        float* cr = C + (size_t)(bm + tr + i) * N + bn + tc;
        *(float4*)(cr)     = make_float4(o0.x, o0.y, o1.x, o1.y);
        *(float4*)(cr + 4) = make_float4(o2.x, o2.y, o3.x, o3.y);
    }
}

// ---------------- alpha/beta: sigmoid(x @ [Wa|Wb] + [ba|bb]) -------------------
// 64 rows per block; [Wa|Wb] interleaved in 128KB dynamic smem as Ws[k][32].
__global__ __launch_bounds__(256)
void ab_kernel(const float* __restrict__ x,
               const float* __restrict__ Wa, const float* __restrict__ ba,
               const float* __restrict__ Wb, const float* __restrict__ bb,
               float* __restrict__ alpha, float* __restrict__ beta){
    extern __shared__ float Ws[];   // [1024][32]
    const int tid = threadIdx.x;
    for (int idx = tid; idx < DMx * 32; idx += 256){
        int k = idx >> 5, cc = idx & 31;
        Ws[idx] = (cc < 16) ? Wa[k * Hh + cc] : Wb[k * Hh + (cc - 16)];
    }
    __syncthreads();
    const int r  = tid >> 2;           // 0..63
    const int cg = tid & 3;            // column group: cols cg*8..cg*8+7
    const int row = blockIdx.x * 64 + r;
    const float* xr = x + (size_t)row * DMx;
    ull acc4[4] = {0ull, 0ull, 0ull, 0ull};
    const ull* wp0 = (const ull*)(Ws + cg * 8);
    #pragma unroll 8
    for (int k = 0; k < DMx; k++){
        ull xv = pack_dup(xr[k]);
        const ull* wp = wp0 + k * 16;  // 32 floats per row -> 16 ulls
        ffma2(acc4[0], xv, wp[0]);
        ffma2(acc4[1], xv, wp[1]);
        ffma2(acc4[2], xv, wp[2]);
        ffma2(acc4[3], xv, wp[3]);
    }
    #pragma unroll
    for (int j = 0; j < 4; j++){
        float lo = __uint_as_float((unsigned)(acc4[j] & 0xffffffffull));
        float hi = __uint_as_float((unsigned)(acc4[j] >> 32));
        #pragma unroll
        for (int p = 0; p < 2; p++){
            float v = p ? hi : lo;
            int cc = cg * 8 + j * 2 + p;
            float bias = (cc < 16) ? ba[cc] : bb[cc - 16];
            float sig = 1.f / (1.f + expf(-(v + bias)));
            if (cc < 16) alpha[(size_t)row * Hh + cc] = sig;
            else         beta [(size_t)row * Hh + cc - 16] = sig;
        }
    }
}

// ---------------- K1: intra-chunk attention + chunk summary --------------------
// grid (NCH, BH). Dynamic smem: Qs/Ks/Vs [64][65] + slg/sb/sw [64].
__global__ __launch_bounds__(256)
void chunk_intra(const float* __restrict__ Q, const float* __restrict__ K,
                 const float* __restrict__ V,
                 const float* __restrict__ alpha, const float* __restrict__ beta,
                 float* __restrict__ Yout, float* __restrict__ U,
                 float* __restrict__ Gout, float* __restrict__ gt_out){
    extern __shared__ float sm[];
    float* Qs  = sm;            // 64*65, later reused as P
    float* Ks  = sm + 4160;
    float* Vs  = sm + 8320;
    float* slg = sm + 12480;    // 64
    float* sb  = sm + 12544;    // 64
    float* sw  = sm + 12608;    // 64

    const int c  = blockIdx.x;
    const int bh = blockIdx.y;
    const int b  = bh >> 4, h = bh & 15;
    const int tid = threadIdx.x;
    const size_t base = ((size_t)(b * Tsz + c * CH) * Hh + h) * Dd;

    // loads: row r (=t within chunk), 16 cols per thread
    {
        const int r = tid >> 2, quad = tid & 3;
        const size_t off = base + (size_t)r * INNERx + quad * 16;
        float4 q0 = *(const float4*)(Q + off),     q1 = *(const float4*)(Q + off + 4);
        float4 q2 = *(const float4*)(Q + off + 8), q3 = *(const float4*)(Q + off + 12);
        float4 k0 = *(const float4*)(K + off),     k1 = *(const float4*)(K + off + 4);
        float4 k2 = *(const float4*)(K + off + 8), k3 = *(const float4*)(K + off + 12);
        float4 v0 = *(const float4*)(V + off),     v1 = *(const float4*)(V + off + 4);
        float4 v2 = *(const float4*)(V + off + 8), v3 = *(const float4*)(V + off + 12);
        // K row norm (4 threads per row)
        float ss = k0.x*k0.x + k0.y*k0.y + k0.z*k0.z + k0.w*k0.w
                 + k1.x*k1.x + k1.y*k1.y + k1.z*k1.z + k1.w*k1.w
                 + k2.x*k2.x + k2.y*k2.y + k2.z*k2.z + k2.w*k2.w
                 + k3.x*k3.x + k3.y*k3.y + k3.z*k3.z + k3.w*k3.w;
        ss += __shfl_xor_sync(0xffffffffu, ss, 1);
        ss += __shfl_xor_sync(0xffffffffu, ss, 2);
        float inv = 1.f / fmaxf(sqrtf(ss), 1e-12f);
        float* qr = Qs + r * 65 + quad * 16;
        float* kr = Ks + r * 65 + quad * 16;
        float* vr = Vs + r * 65 + quad * 16;
        qr[0]=q0.x; qr[1]=q0.y; qr[2]=q0.z; qr[3]=q0.w;
        qr[4]=q1.x; qr[5]=q1.y; qr[6]=q1.z; qr[7]=q1.w;
        qr[8]=q2.x; qr[9]=q2.y; qr[10]=q2.z; qr[11]=q2.w;
        qr[12]=q3.x; qr[13]=q3.y; qr[14]=q3.z; qr[15]=q3.w;
        kr[0]=k0.x*inv; kr[1]=k0.y*inv; kr[2]=k0.z*inv; kr[3]=k0.w*inv;
        kr[4]=k1.x*inv; kr[5]=k1.y*inv; kr[6]=k1.z*inv; kr[7]=k1.w*inv;
        kr[8]=k2.x*inv; kr[9]=k2.y*inv; kr[10]=k2.z*inv; kr[11]=k2.w*inv;
        kr[12]=k3.x*inv; kr[13]=k3.y*inv; kr[14]=k3.z*inv; kr[15]=k3.w*inv;
        vr[0]=v0.x; vr[1]=v0.y; vr[2]=v0.z; vr[3]=v0.w;
        vr[4]=v1.x; vr[5]=v1.y; vr[6]=v1.z; vr[7]=v1.w;
        vr[8]=v2.x; vr[9]=v2.y; vr[10]=v2.z; vr[11]=v2.w;
        vr[12]=v3.x; vr[13]=v3.y; vr[14]=v3.z; vr[15]=v3.w;
    }
    if (tid < 64){
        size_t gidx = (size_t)(b * Tsz + c * CH + tid) * Hh + h;
        slg[tid] = __logf(alpha[gidx]);
        sb[tid]  = beta[gidx];
    }
    __syncthreads();
    if (tid == 0){
        float s = 0.f;
        for (int j = 0; j < CH; j++){ s += slg[j]; slg[j] = s; }
    }
    __syncthreads();
    if (tid < 64){
        float lg_last = slg[63];
        sw[tid] = __expf(lg_last - slg[tid]) * sb[tid];
        float g = __expf(slg[tid]);
        gt_out[(size_t)bh * Tsz + c * CH + tid] = g;
        if (tid == 63) Gout[bh * NCH + c] = g;
    }
    __syncthreads();

    const int tr  = (tid >> 4) << 2;   // 4 rows (tau)
    const int tc4 = (tid & 15) << 2;   // 4 cols

    // phase M: M[tau][j] = q_tau . k_j (into registers)
    float accM[4][4];
    #pragma unroll
    for (int i=0;i<4;i++)
        #pragma unroll
        for (int j=0;j<4;j++) accM[i][j] = 0.f;
    #pragma unroll 4
    for (int d = 0; d < Dd; d++){
        float qf[4], kf[4];
        #pragma unroll
        for (int i=0;i<4;i++) qf[i] = Qs[(tr+i)*65 + d];
        #pragma unroll
        for (int j=0;j<4;j++) kf[j] = Ks[(tc4+j)*65 + d];
        #pragma unroll
        for (int i=0;i<4;i++)
            #pragma unroll
            for (int j=0;j<4;j++) accM[i][j] = fmaf(qf[i], kf[j], accM[i][j]);
    }
    __syncthreads();   // all reads of Qs done
    // write gated+masked P into Qs region
    #pragma unroll
    for (int i=0;i<4;i++){
        int tau = tr + i;
        float lgt = slg[tau];
        #pragma unroll
        for (int j=0;j<4;j++){
            int jj = tc4 + j;
            float p = 0.f;
            if (tau >= jj) p = __expf(lgt - slg[jj]) * sb[jj] * accM[i][j];
            Qs[tau*65 + jj] = p;
        }
    }
    __syncthreads();

    // phase Y: Yintra = P @ V ; phase U: U = V^T diag(w) K
    float accY[4][4], accU[4][4];
    #pragma unroll
    for (int i=0;i<4;i++)
        #pragma unroll
        for (int j=0;j<4;j++){ accY[i][j] = 0.f; accU[i][j] = 0.f; }
    #pragma unroll 2
    for (int j = 0; j < CH; j++){
        float wj = sw[j];
        float pf[4], vf[4], vu[4], kf[4];
        #pragma unroll
        for (int i=0;i<4;i++) pf[i] = Qs[(tr+i)*65 + j];
        #pragma unroll
        for (int d=0;d<4;d++) vf[d] = Vs[j*65 + tc4 + d];
        #pragma unroll
        for (int i=0;i<4;i++) vu[i] = Vs[j*65 + tr + i] * wj;
        #pragma unroll
        for (int d=0;d<4;d++) kf[d] = Ks[j*65 + tc4 + d];
        #pragma unroll
        for (int i=0;i<4;i++)
            #pragma unroll
            for (int d=0;d<4;d++){
                accY[i][d] = fmaf(pf[i], vf[d], accY[i][d]);
                accU[i][d] = fmaf(vu[i], kf[d], accU[i][d]);
            }
    }
    #pragma unroll
    for (int i=0;i<4;i++){
        float* yr = Yout + base + (size_t)(tr + i) * INNERx + tc4;
        *(float4*)yr = make_float4(accY[i][0], accY[i][1], accY[i][2], accY[i][3]);
        float* ur = U + ((size_t)(bh * NCH + c) * 4096) + (tr + i) * 64 + tc4;
        *(float4*)ur = make_float4(accU[i][0], accU[i][1], accU[i][2], accU[i][3]);
    }
}

// ---------------- K2: chunk-level state scan -----------------------------------
__global__ __launch_bounds__(256)
void chunk_scan(const float* __restrict__ U, const float* __restrict__ G,
                const float* __restrict__ state0,
                float* __restrict__ Sc, float* __restrict__ stateOut){
    const int bh = blockIdx.x;
    const int tid = threadIdx.x;
    float S[16];
    const size_t bs = (size_t)bh * 4096;
    #pragma unroll
    for (int j = 0; j < 16; j++) S[j] = state0[bs + j * 256 + tid];
    for (int c = 0; c < NCH; c++){
        const size_t uc = ((size_t)(bh * NCH + c)) * 4096;
        float g = __ldg(&G[bh * NCH + c]);
        float u[16];
        #pragma unroll
        for (int j = 0; j < 16; j++) u[j] = U[uc + j * 256 + tid];
        #pragma unroll
        for (int j = 0; j < 16; j++){
            Sc[uc + j * 256 + tid] = S[j];
            S[j] = fmaf(g, S[j], u[j]);
        }
    }
    #pragma unroll
    for (int j = 0; j < 16; j++) stateOut[bs + j * 256 + tid] = S[j];
}

// ---------------- K3: add inter-chunk contribution Y += diag(g) Q S^T ----------
__global__ __launch_bounds__(256)
void chunk_inter(const float* __restrict__ Q, const float* __restrict__ Sc,
                 const float* __restrict__ gt, float* __restrict__ Y){
    __shared__ float Qs[64*65];
    __shared__ float Ss[64*65];
    __shared__ float sg[64];
    const int c  = blockIdx.x;
    const int bh = blockIdx.y;
    const int b  = bh >> 4, h = bh & 15;
    const int tid = threadIdx.x;
    const size_t base = ((size_t)(b * Tsz + c * CH) * Hh + h) * Dd;
    {
        const int r = tid >> 2, quad = tid & 3;
        const size_t off = base + (size_t)r * INNERx + quad * 16;
        const size_t soff = ((size_t)(bh * NCH + c)) * 4096 + r * 64 + quad * 16;
        #pragma unroll
        for (int l = 0; l < 16; l += 4){
            float4 qv = *(const float4*)(Q + off + l);
            float4 sv = *(const float4*)(Sc + soff + l);
            float* qr = Qs + r * 65 + quad * 16 + l;
            float* sr = Ss + r * 65 + quad * 16 + l;
            qr[0]=qv.x; qr[1]=qv.y; qr[2]=qv.z; qr[3]=qv.w;
            sr[0]=sv.x; sr[1]=sv.y; sr[2]=sv.z; sr[3]=sv.w;
        }
    }
    if (tid < 64) sg[tid] = gt[(size_t)bh * Tsz + c * CH + tid];
    __syncthreads();
    const int tr  = (tid >> 4) << 2;   // tau rows
    const int tci = (tid & 15) << 2;   // i (v-dim) cols
    float acc[4][4];
    #pragma unroll
    for (int i=0;i<4;i++)
        #pragma unroll
        for (int j=0;j<4;j++) acc[i][j] = 0.f;
    #pragma unroll 4
    for (int j = 0; j < Dd; j++){
        float qf[4], sf[4];
        #pragma unroll
        for (int i=0;i<4;i++) qf[i] = Qs[(tr+i)*65 + j];
        #pragma unroll
        for (int k=0;k<4;k++) sf[k] = Ss[(tci+k)*65 + j];
        #pragma unroll
        for (int i=0;i<4;i++)
            #pragma unroll
            for (int k=0;k<4;k++) acc[i][k] = fmaf(qf[i], sf[k], acc[i][k]);
    }
    #pragma unroll
    for (int i=0;i<4;i++){
        float gt_ = sg[tr + i];
        float* yr = Y + base + (size_t)(tr + i) * INNERx + tci;
        float4 old = *(float4*)yr;
        old.x = fmaf(gt_, acc[i][0], old.x);
        old.y = fmaf(gt_, acc[i][1], old.y);
        old.z = fmaf(gt_, acc[i][2], old.z);
        old.w = fmaf(gt_, acc[i][3], old.w);
        *(float4*)yr = old;
    }
}

// ---------------- launcher -----------------------------------------------------
extern "C" void kernel_launch(void* const* d_in, const int* in_sizes, int n_in,
                              void* d_out, int out_size){
    const float* x     = (const float*)d_in[0];
    const float* state = (const float*)d_in[1];
    const float* Wq    = (const float*)d_in[2];
    const float* Wk    = (const float*)d_in[3];
    const float* Wv    = (const float*)d_in[4];
    const float* Wa    = (const float*)d_in[5];
    const float* ba    = (const float*)d_in[6];
    const float* Wb    = (const float*)d_in[7];
    const float* bb    = (const float*)d_in[8];
    const float* Wo    = (const float*)d_in[9];

    float* out      = (float*)d_out;
    float* stateOut = out + (size_t)ROWS * DMx;

    float *Q, *K, *V, *Y, *al, *be, *U, *Sc, *G, *gt;
    cudaGetSymbolAddress((void**)&Q,  g_Q);
    cudaGetSymbolAddress((void**)&K,  g_K);
    cudaGetSymbolAddress((void**)&V,  g_V);
    cudaGetSymbolAddress((void**)&Y,  g_Y);
    cudaGetSymbolAddress((void**)&al, g_alpha);
    cudaGetSymbolAddress((void**)&be, g_beta);
    cudaGetSymbolAddress((void**)&U,  g_U);
    cudaGetSymbolAddress((void**)&Sc, g_Sc);
    cudaGetSymbolAddress((void**)&G,  g_G);
    cudaGetSymbolAddress((void**)&gt, g_gt);

    cudaFuncSetAttribute(ab_kernel,   cudaFuncAttributeMaxDynamicSharedMemorySize, DMx*32*4);
    cudaFuncSetAttribute(chunk_intra, cudaFuncAttributeMaxDynamicSharedMemorySize, 12672*4);

    dim3 gqkv(INNERx / 128, ROWS / 128);
    sgemm_db<<<gqkv, 256>>>(x, Wq, Q, ROWS, INNERx, DMx);
    sgemm_db<<<gqkv, 256>>>(x, Wk, K, ROWS, INNERx, DMx);
    sgemm_db<<<gqkv, 256>>>(x, Wv, V, ROWS, INNERx, DMx);
    ab_kernel<<<ROWS / 64, 256, DMx*32*4>>>(x, Wa, ba, Wb, bb, al, be);
    chunk_intra<<<dim3(NCH, BH), 256, 12672*4>>>(Q, K, V, al, be, Y, U, G, gt);
    chunk_scan<<<BH, 256>>>(U, G, state, Sc, stateOut);
    chunk_inter<<<dim3(NCH, BH), 256>>>(Q, Sc, gt, Y);
    dim3 gout(DMx / 128, ROWS / 128);
    sgemm_db<<<gout, 256>>>(Y, Wo, out, ROWS, DMx, INNERx);
}

// round 5
// speedup vs baseline: 4.0878x; 2.2672x over previous
#include <cuda_runtime.h>
#include <cuda_bf16.h>
#include <math.h>
#include <cstdint>

#define Bsz 4
#define Tsz 2048
#define DMx 1024
#define Hh  16
#define Dd  64
#define INNERx 1024
#define ROWS (Bsz*Tsz)   // 8192
#define CH 64
#define NCH (Tsz/CH)     // 32
#define BH (Bsz*Hh)      // 64
#define KDIM 1024
#define NCHUNKS 48       // 3*KDIM/64 (3-term split, K-chunk 64)

typedef unsigned long long ull;
typedef __nv_bfloat16 bf16;

// ---------------- scratch ----------------
__device__ float g_Q[ROWS*INNERx];
__device__ float g_K[ROWS*INNERx];
__device__ float g_V[ROWS*INNERx];
__device__ float g_Y[ROWS*INNERx];
__device__ float g_alpha[ROWS*Hh];
__device__ float g_beta[ROWS*Hh];
__device__ float g_U[BH*NCH*Dd*Dd];
__device__ float g_Sc[BH*NCH*Dd*Dd];
__device__ float g_G[BH*NCH];
__device__ float g_gt[BH*Tsz];
__device__ bf16 g_xh[ROWS*DMx];
__device__ bf16 g_xl[ROWS*DMx];
__device__ bf16 g_yh[ROWS*INNERx];
__device__ bf16 g_yl[ROWS*INNERx];
__device__ bf16 g_wqh[DMx*INNERx], g_wql[DMx*INNERx];
__device__ bf16 g_wkh[DMx*INNERx], g_wkl[DMx*INNERx];
__device__ bf16 g_wvh[DMx*INNERx], g_wvl[DMx*INNERx];
__device__ bf16 g_woh[INNERx*DMx], g_wol[INNERx*DMx];

// ---------------- helpers ----------------
__device__ __forceinline__ uint32_t smem_to_u32(const void* p){
    uint32_t a;
    asm("{ .reg .u64 t; cvta.to.shared.u64 t, %1; cvt.u32.u64 %0, t; }" : "=r"(a) : "l"(p));
    return a;
}
__device__ __forceinline__ void cp_async16(uint32_t dst, const void* src){
    asm volatile("cp.async.cg.shared.global [%0], [%1], 16;" :: "r"(dst), "l"(src));
}
#define CP_COMMIT() asm volatile("cp.async.commit_group;" ::: "memory")
#define CP_WAIT(n)  asm volatile("cp.async.wait_group %0;" :: "n"(n) : "memory")

__device__ __forceinline__ void ldsm_x4(uint32_t* r, uint32_t addr){
    asm volatile("ldmatrix.sync.aligned.m8n8.x4.shared.b16 {%0,%1,%2,%3}, [%4];"
        : "=r"(r[0]), "=r"(r[1]), "=r"(r[2]), "=r"(r[3]) : "r"(addr));
}
__device__ __forceinline__ void mma_bf16(float* c, const uint32_t* a, const uint32_t* b){
    asm volatile(
        "mma.sync.aligned.m16n8k16.row.col.f32.bf16.bf16.f32 "
        "{%0,%1,%2,%3}, {%4,%5,%6,%7}, {%8,%9}, {%0,%1,%2,%3};"
        : "+f"(c[0]), "+f"(c[1]), "+f"(c[2]), "+f"(c[3])
        : "r"(a[0]), "r"(a[1]), "r"(a[2]), "r"(a[3]), "r"(b[0]), "r"(b[1]));
}
__device__ __forceinline__ ull pack_dup(float a){
    ull r; unsigned int u = __float_as_uint(a);
    asm("mov.b64 %0, {%1, %1};" : "=l"(r) : "r"(u));
    return r;
}
__device__ __forceinline__ void ffma2(ull& d, ull a, ull b){
    asm("fma.rn.f32x2 %0, %1, %2, %3;" : "=l"(d) : "l"(a), "l"(b), "l"(d));
}

// ---------------- conversion kernels ----------------
__global__ __launch_bounds__(256)
void conv_split(const float* __restrict__ src, bf16* __restrict__ h,
                bf16* __restrict__ l){
    const size_t i = (size_t)blockIdx.x * 256 + threadIdx.x;
    float4 v = *(const float4*)(src + i * 4);
    bf16 h0 = __float2bfloat16(v.x), h1 = __float2bfloat16(v.y);
    bf16 h2 = __float2bfloat16(v.z), h3 = __float2bfloat16(v.w);
    bf16 l0 = __float2bfloat16(v.x - __bfloat162float(h0));
    bf16 l1 = __float2bfloat16(v.y - __bfloat162float(h1));
    bf16 l2 = __float2bfloat16(v.z - __bfloat162float(h2));
    bf16 l3 = __float2bfloat16(v.w - __bfloat162float(h3));
    __nv_bfloat162* hp = (__nv_bfloat162*)(h + i * 4);
    __nv_bfloat162* lp = (__nv_bfloat162*)(l + i * 4);
    hp[0] = __nv_bfloat162{h0, h1}; hp[1] = __nv_bfloat162{h2, h3};
    lp[0] = __nv_bfloat162{l0, l1}; lp[1] = __nv_bfloat162{l2, l3};
}

// W[K][N] (1024x1024) -> T[N][K] split hi/lo
__global__ __launch_bounds__(256)
void trans_split(const float* __restrict__ W, bf16* __restrict__ Th,
                 bf16* __restrict__ Tl){
    __shared__ float ts[32][33];
    const int k0 = blockIdx.y * 32, n0 = blockIdx.x * 32;
    const int tx = threadIdx.x & 31, ty = threadIdx.x >> 5;
    for (int i = ty; i < 32; i += 8)
        ts[i][tx] = W[(size_t)(k0 + i) * 1024 + n0 + tx];
    __syncthreads();
    for (int i = ty; i < 32; i += 8){
        float v = ts[tx][i];
        bf16 h = __float2bfloat16(v);
        bf16 l = __float2bfloat16(v - __bfloat162float(h));
        Th[(size_t)(n0 + i) * 1024 + k0 + tx] = h;
        Tl[(size_t)(n0 + i) * 1024 + k0 + tx] = l;
    }
}

// ---------------- bf16-split mma.sync GEMM: C = A @ B^T ------------------------
// A split (Ah,Al) [M][1024] bf16; B split (Bh,Bl) [N][1024] (pre-transposed).
// Extended K = 3072 via phases (Ah,Bh),(Al,Bh),(Ah,Bl). fp32 accum in registers.
// 128x128 CTA tile, 8 warps (2x4) of 64x32, K-chunk 64, 2-stage cp.async.
#define STAGE_BYTES 32768          // A 16KB + B 16KB per stage
#define GEMM_SMEM   (2*STAGE_BYTES)

__global__ __launch_bounds__(256, 2)
void gemm_mma(const bf16* __restrict__ Ah, const bf16* __restrict__ Al,
              const bf16* __restrict__ Bh, const bf16* __restrict__ Bl,
              float* __restrict__ C, int N){
    extern __shared__ __align__(128) char sm[];
    const uint32_t sb = smem_to_u32(sm);
    const int tid = threadIdx.x, lane = tid & 31, wid = tid >> 5;
    const int wm = wid >> 2, wn = wid & 3;
    const int bm = blockIdx.y * 128, bn = blockIdx.x * 128;

    float acc[4][4][4];
    #pragma unroll
    for (int mt = 0; mt < 4; mt++)
        #pragma unroll
        for (int nt = 0; nt < 4; nt++)
            #pragma unroll
            for (int e = 0; e < 4; e++) acc[mt][nt][e] = 0.f;

    const int urow = tid >> 3, uu = tid & 7;            // thread's 16B unit base
    const int ubo = urow * 128 + uu * 16;
    const uint32_t uph = ubo ^ ((ubo >> 3) & 0x70);     // swizzled dst offset

    auto issue_stage = [&](int buf, int c){
        const int p = c >> 4, kk0 = (c & 15) << 6;
        const bf16* As = (p == 1) ? Al : Ah;
        const bf16* Bs = (p == 2) ? Bl : Bh;
        const uint32_t abase = sb + buf * STAGE_BYTES;
        const uint32_t bbase = abase + 16384;
        #pragma unroll
        for (int i = 0; i < 4; i++){
            const int row = urow + i * 32;
            const uint32_t dph = uph + i * 4096;
            cp_async16(abase + dph, As + (size_t)(bm + row) * KDIM + kk0 + uu * 8);
            cp_async16(bbase + dph, Bs + (size_t)(bn + row) * KDIM + kk0 + uu * 8);
        }
    };

    issue_stage(0, 0); CP_COMMIT();
    int buf = 0;
    for (int c = 0; c < NCHUNKS; c++){
        if (c + 1 < NCHUNKS){ issue_stage(buf ^ 1, c + 1); CP_COMMIT(); CP_WAIT(1); }
        else                 { CP_WAIT(0); }
        __syncthreads();
        const uint32_t abase = sb + buf * STAGE_BYTES;
        const uint32_t bbase = abase + 16384;
        #pragma unroll
        for (int ks = 0; ks < 4; ks++){
            uint32_t afr[4][4];
            #pragma unroll
            for (int mt = 0; mt < 4; mt++){
                const int row = wm * 64 + mt * 16 + (lane & 15);
                const int bo = row * 128 + ks * 32 + ((lane >> 4) << 4);
                ldsm_x4(afr[mt], abase + (bo ^ ((bo >> 3) & 0x70)));
            }
            uint32_t bfr[2][4];
            #pragma unroll
            for (int np = 0; np < 2; np++){
                const int g = lane >> 3;
                const int row = wn * 32 + np * 16 + ((g >> 1) << 3) + (lane & 7);
                const int bo = row * 128 + ks * 32 + ((g & 1) << 4);
                ldsm_x4(bfr[np], bbase + (bo ^ ((bo >> 3) & 0x70)));
            }
            #pragma unroll
            for (int mt = 0; mt < 4; mt++)
                #pragma unroll
                for (int nt = 0; nt < 4; nt++)
                    mma_bf16(acc[mt][nt], afr[mt], &bfr[nt >> 1][(nt & 1) * 2]);
        }
        __syncthreads();
        buf ^= 1;
    }

    const int r0 = lane >> 2, cb = (lane & 3) << 1;
    #pragma unroll
    for (int mt = 0; mt < 4; mt++){
        const int grow = bm + wm * 64 + mt * 16 + r0;
        #pragma unroll
        for (int nt = 0; nt < 4; nt++){
            const int gcol = bn + wn * 32 + nt * 8 + cb;
            *(float2*)(C + (size_t)grow * N + gcol) =
                make_float2(acc[mt][nt][0], acc[mt][nt][1]);
            *(float2*)(C + (size_t)(grow + 8) * N + gcol) =
                make_float2(acc[mt][nt][2], acc[mt][nt][3]);
        }
    }
}

// ---------------- alpha/beta gate GEMM ----------------
__global__ __launch_bounds__(256)
void ab_kernel(const float* __restrict__ x,
               const float* __restrict__ Wa, const float* __restrict__ ba,
               const float* __restrict__ Wb, const float* __restrict__ bb,
               float* __restrict__ alpha, float* __restrict__ beta){
    __shared__ float xs[32][40];
    __shared__ float Ws[32][32];
    const int tid = threadIdx.x;
    const int r = tid >> 3, sub = tid & 7;
    const int row0 = blockIdx.x * 32;
    ull acc[2] = {0ull, 0ull};
    for (int k0 = 0; k0 < DMx; k0 += 32){
        #pragma unroll
        for (int q = 0; q < 4; q++){
            int idx = tid + q * 256;
            int kk = idx >> 5, cc = idx & 31;
            Ws[kk][cc] = (cc < 16) ? Wa[(size_t)(k0 + kk) * Hh + cc]
                                   : Wb[(size_t)(k0 + kk) * Hh + cc - 16];
        }
        {
            const int rr = tid >> 3, seg = tid & 7;
            float4 v = *(const float4*)(x + (size_t)(row0 + rr) * DMx + k0 + seg * 4);
            *(float4*)&xs[rr][seg * 4] = v;
        }
        __syncthreads();
        #pragma unroll
        for (int kk = 0; kk < 32; kk++){
            ull xv = pack_dup(xs[r][kk]);
            const ull* wp = (const ull*)&Ws[kk][sub * 4];
            ffma2(acc[0], xv, wp[0]);
            ffma2(acc[1], xv, wp[1]);
        }
        __syncthreads();
    }
    #pragma unroll
    for (int j = 0; j < 2; j++){
        float lo = __uint_as_float((unsigned)(acc[j] & 0xffffffffull));
        float hi = __uint_as_float((unsigned)(acc[j] >> 32));
        #pragma unroll
        for (int p = 0; p < 2; p++){
            float v = p ? hi : lo;
            int cc = sub * 4 + j * 2 + p;
            float bias = (cc < 16) ? ba[cc] : bb[cc - 16];
            float sig = 1.f / (1.f + expf(-(v + bias)));
            if (cc < 16) alpha[(size_t)(row0 + r) * Hh + cc] = sig;
            else         beta [(size_t)(row0 + r) * Hh + cc - 16] = sig;
        }
    }
}

// ---------------- K1: intra-chunk attention + chunk summary --------------------
__global__ __launch_bounds__(256)
void chunk_intra(const float* __restrict__ Q, const float* __restrict__ K,
                 const float* __restrict__ V,
                 const float* __restrict__ alpha, const float* __restrict__ beta,
                 float* __restrict__ Yout, float* __restrict__ U,
                 float* __restrict__ Gout, float* __restrict__ gt_out){
    extern __shared__ float smf[];
    float* Qs  = smf;
    float* Ks  = smf + 4160;
    float* Vs  = smf + 8320;
    float* slg = smf + 12480;
    float* sb  = smf + 12544;
    float* sw  = smf + 12608;

    const int c  = blockIdx.x;
    const int bh = blockIdx.y;
    const int b  = bh >> 4, h = bh & 15;
    const int tid = threadIdx.x;
    const size_t base = ((size_t)(b * Tsz + c * CH) * Hh + h) * Dd;

    {
        const int r = tid >> 2, quad = tid & 3;
        const size_t off = base + (size_t)r * INNERx + quad * 16;
        float4 q0 = *(const float4*)(Q + off),     q1 = *(const float4*)(Q + off + 4);
        float4 q2 = *(const float4*)(Q + off + 8), q3 = *(const float4*)(Q + off + 12);
        float4 k0 = *(const float4*)(K + off),     k1 = *(const float4*)(K + off + 4);
        float4 k2 = *(const float4*)(K + off + 8), k3 = *(const float4*)(K + off + 12);
        float4 v0 = *(const float4*)(V + off),     v1 = *(const float4*)(V + off + 4);
        float4 v2 = *(const float4*)(V + off + 8), v3 = *(const float4*)(V + off + 12);
        float ss = k0.x*k0.x + k0.y*k0.y + k0.z*k0.z + k0.w*k0.w
                 + k1.x*k1.x + k1.y*k1.y + k1.z*k1.z + k1.w*k1.w
                 + k2.x*k2.x + k2.y*k2.y + k2.z*k2.z + k2.w*k2.w
                 + k3.x*k3.x + k3.y*k3.y + k3.z*k3.z + k3.w*k3.w;
        ss += __shfl_xor_sync(0xffffffffu, ss, 1);
        ss += __shfl_xor_sync(0xffffffffu, ss, 2);
        float inv = 1.f / fmaxf(sqrtf(ss), 1e-12f);
        float* qr = Qs + r * 65 + quad * 16;
        float* kr = Ks + r * 65 + quad * 16;
        float* vr = Vs + r * 65 + quad * 16;
        qr[0]=q0.x; qr[1]=q0.y; qr[2]=q0.z; qr[3]=q0.w;
        qr[4]=q1.x; qr[5]=q1.y; qr[6]=q1.z; qr[7]=q1.w;
        qr[8]=q2.x; qr[9]=q2.y; qr[10]=q2.z; qr[11]=q2.w;
        qr[12]=q3.x; qr[13]=q3.y; qr[14]=q3.z; qr[15]=q3.w;
        kr[0]=k0.x*inv; kr[1]=k0.y*inv; kr[2]=k0.z*inv; kr[3]=k0.w*inv;
        kr[4]=k1.x*inv; kr[5]=k1.y*inv; kr[6]=k1.z*inv; kr[7]=k1.w*inv;
        kr[8]=k2.x*inv; kr[9]=k2.y*inv; kr[10]=k2.z*inv; kr[11]=k2.w*inv;
        kr[12]=k3.x*inv; kr[13]=k3.y*inv; kr[14]=k3.z*inv; kr[15]=k3.w*inv;
        vr[0]=v0.x; vr[1]=v0.y; vr[2]=v0.z; vr[3]=v0.w;
        vr[4]=v1.x; vr[5]=v1.y; vr[6]=v1.z; vr[7]=v1.w;
        vr[8]=v2.x; vr[9]=v2.y; vr[10]=v2.z; vr[11]=v2.w;
        vr[12]=v3.x; vr[13]=v3.y; vr[14]=v3.z; vr[15]=v3.w;
    }
    if (tid < 64){
        size_t gidx = (size_t)(b * Tsz + c * CH + tid) * Hh + h;
        slg[tid] = __logf(alpha[gidx]);
        sb[tid]  = beta[gidx];
    }
    __syncthreads();
    if (tid == 0){
        float s = 0.f;
        for (int j = 0; j < CH; j++){ s += slg[j]; slg[j] = s; }
    }
    __syncthreads();
    if (tid < 64){
        float lg_last = slg[63];
        sw[tid] = __expf(lg_last - slg[tid]) * sb[tid];
        float g = __expf(slg[tid]);
        gt_out[(size_t)bh * Tsz + c * CH + tid] = g;
        if (tid == 63) Gout[bh * NCH + c] = g;
    }
    __syncthreads();

    const int tr  = (tid >> 4) << 2;
    const int tc4 = (tid & 15) << 2;

    float accM[4][4];
    #pragma unroll
    for (int i=0;i<4;i++)
        #pragma unroll
        for (int j=0;j<4;j++) accM[i][j] = 0.f;
    #pragma unroll 4
    for (int d = 0; d < Dd; d++){
        float qf[4], kf[4];
        #pragma unroll
        for (int i=0;i<4;i++) qf[i] = Qs[(tr+i)*65 + d];
        #pragma unroll
        for (int j=0;j<4;j++) kf[j] = Ks[(tc4+j)*65 + d];
        #pragma unroll
        for (int i=0;i<4;i++)
            #pragma unroll
            for (int j=0;j<4;j++) accM[i][j] = fmaf(qf[i], kf[j], accM[i][j]);
    }
    __syncthreads();
    #pragma unroll
    for (int i=0;i<4;i++){
        int tau = tr + i;
        float lgt = slg[tau];
        #pragma unroll
        for (int j=0;j<4;j++){
            int jj = tc4 + j;
            float p = 0.f;
            if (tau >= jj) p = __expf(lgt - slg[jj]) * sb[jj] * accM[i][j];
            Qs[tau*65 + jj] = p;
        }
    }
    __syncthreads();

    float accY[4][4], accU[4][4];
    #pragma unroll
    for (int i=0;i<4;i++)
        #pragma unroll
        for (int j=0;j<4;j++){ accY[i][j] = 0.f; accU[i][j] = 0.f; }
    #pragma unroll 2
    for (int j = 0; j < CH; j++){
        float wj = sw[j];
        float pf[4], vf[4], vu[4], kf[4];
        #pragma unroll
        for (int i=0;i<4;i++) pf[i] = Qs[(tr+i)*65 + j];
        #pragma unroll
        for (int d=0;d<4;d++) vf[d] = Vs[j*65 + tc4 + d];
        #pragma unroll
        for (int i=0;i<4;i++) vu[i] = Vs[j*65 + tr + i] * wj;
        #pragma unroll
        for (int d=0;d<4;d++) kf[d] = Ks[j*65 + tc4 + d];
        #pragma unroll
        for (int i=0;i<4;i++)
            #pragma unroll
            for (int d=0;d<4;d++){
                accY[i][d] = fmaf(pf[i], vf[d], accY[i][d]);
                accU[i][d] = fmaf(vu[i], kf[d], accU[i][d]);
            }
    }
    #pragma unroll
    for (int i=0;i<4;i++){
        float* yr = Yout + base + (size_t)(tr + i) * INNERx + tc4;
        *(float4*)yr = make_float4(accY[i][0], accY[i][1], accY[i][2], accY[i][3]);
        float* ur = U + ((size_t)(bh * NCH + c) * 4096) + (tr + i) * 64 + tc4;
        *(float4*)ur = make_float4(accU[i][0], accU[i][1], accU[i][2], accU[i][3]);
    }
}

// ---------------- K2: chunk-level state scan -----------------------------------
__global__ __launch_bounds__(256)
void chunk_scan(const float* __restrict__ U, const float* __restrict__ G,
                const float* __restrict__ state0,
                float* __restrict__ Sc, float* __restrict__ stateOut){
    const int bh = blockIdx.x;
    const int tid = threadIdx.x;
    float S[16];
    const size_t bs = (size_t)bh * 4096;
    #pragma unroll
    for (int j = 0; j < 16; j++) S[j] = state0[bs + j * 256 + tid];
    for (int c = 0; c < NCH; c++){
        const size_t uc = ((size_t)(bh * NCH + c)) * 4096;
        float g = __ldg(&G[bh * NCH + c]);
        float u[16];
        #pragma unroll
        for (int j = 0; j < 16; j++) u[j] = U[uc + j * 256 + tid];
        #pragma unroll
        for (int j = 0; j < 16; j++){
            Sc[uc + j * 256 + tid] = S[j];
            S[j] = fmaf(g, S[j], u[j]);
        }
    }
    #pragma unroll
    for (int j = 0; j < 16; j++) stateOut[bs + j * 256 + tid] = S[j];
}

// ---------------- K3: Y += diag(g) Q S^T ; emit bf16 hi/lo split of Y ----------
__global__ __launch_bounds__(256)
void chunk_inter(const float* __restrict__ Q, const float* __restrict__ Sc,
                 const float* __restrict__ gt, const float* __restrict__ Y,
                 bf16* __restrict__ Yh, bf16* __restrict__ Yl){
    __shared__ float Qs[64*65];
    __shared__ float Ss[64*65];
    __shared__ float sg[64];
    const int c  = blockIdx.x;
    const int bh = blockIdx.y;
    const int b  = bh >> 4, h = bh & 15;
    const int tid = threadIdx.x;
    const size_t base = ((size_t)(b * Tsz + c * CH) * Hh + h) * Dd;
    {
        const int r = tid >> 2, quad = tid & 3;
        const size_t off = base + (size_t)r * INNERx + quad * 16;
        const size_t soff = ((size_t)(bh * NCH + c)) * 4096 + r * 64 + quad * 16;
        #pragma unroll
        for (int l = 0; l < 16; l += 4){
            float4 qv = *(const float4*)(Q + off + l);
            float4 sv = *(const float4*)(Sc + soff + l);
            float* qr = Qs + r * 65 + quad * 16 + l;
            float* sr = Ss + r * 65 + quad * 16 + l;
            qr[0]=qv.x; qr[1]=qv.y; qr[2]=qv.z; qr[3]=qv.w;
            sr[0]=sv.x; sr[1]=sv.y; sr[2]=sv.z; sr[3]=sv.w;
        }
    }
    if (tid < 64) sg[tid] = gt[(size_t)bh * Tsz + c * CH + tid];
    __syncthreads();
    const int tr  = (tid >> 4) << 2;
    const int tci = (tid & 15) << 2;
    float acc[4][4];
    #pragma unroll
    for (int i=0;i<4;i++)
        #pragma unroll
        for (int j=0;j<4;j++) acc[i][j] = 0.f;
    #pragma unroll 4
    for (int j = 0; j < Dd; j++){
        float qf[4], sf[4];
        #pragma unroll
        for (int i=0;i<4;i++) qf[i] = Qs[(tr+i)*65 + j];
        #pragma unroll
        for (int k=0;k<4;k++) sf[k] = Ss[(tci+k)*65 + j];
        #pragma unroll
        for (int i=0;i<4;i++)
            #pragma unroll
            for (int k=0;k<4;k++) acc[i][k] = fmaf(qf[i], sf[k], acc[i][k]);
    }
    #pragma unroll
    for (int i=0;i<4;i++){
        float gt_ = sg[tr + i];
        const size_t off = base + (size_t)(tr + i) * INNERx + tci;
        float4 old = *(const float4*)(Y + off);
        float f0 = fmaf(gt_, acc[i][0], old.x);
        float f1 = fmaf(gt_, acc[i][1], old.y);
        float f2 = fmaf(gt_, acc[i][2], old.z);
        float f3 = fmaf(gt_, acc[i][3], old.w);
        bf16 h0 = __float2bfloat16(f0), h1 = __float2bfloat16(f1);
        bf16 h2 = __float2bfloat16(f2), h3 = __float2bfloat16(f3);
        bf16 l0 = __float2bfloat16(f0 - __bfloat162float(h0));
        bf16 l1 = __float2bfloat16(f1 - __bfloat162float(h1));
        bf16 l2 = __float2bfloat16(f2 - __bfloat162float(h2));
        bf16 l3 = __float2bfloat16(f3 - __bfloat162float(h3));
        __nv_bfloat162* hp = (__nv_bfloat162*)(Yh + off);
        __nv_bfloat162* lp = (__nv_bfloat162*)(Yl + off);
        hp[0] = __nv_bfloat162{h0, h1}; hp[1] = __nv_bfloat162{h2, h3};
        lp[0] = __nv_bfloat162{l0, l1}; lp[1] = __nv_bfloat162{l2, l3};
    }
}

// ---------------- launcher -----------------------------------------------------
extern "C" void kernel_launch(void* const* d_in, const int* in_sizes, int n_in,
                              void* d_out, int out_size){
    const float* x     = (const float*)d_in[0];
    const float* state = (const float*)d_in[1];
    const float* Wq    = (const float*)d_in[2];
    const float* Wk    = (const float*)d_in[3];
    const float* Wv    = (const float*)d_in[4];
    const float* Wa    = (const float*)d_in[5];
    const float* ba    = (const float*)d_in[6];
    const float* Wb    = (const float*)d_in[7];
    const float* bb    = (const float*)d_in[8];
    const float* Wo    = (const float*)d_in[9];

    float* out      = (float*)d_out;
    float* stateOut = out + (size_t)ROWS * DMx;

    float *Q, *K, *V, *Y, *al, *be, *U, *Sc, *G, *gt;
    bf16 *xh, *xl, *yh, *yl, *wqh, *wql, *wkh, *wkl, *wvh, *wvl, *woh, *wol;
    cudaGetSymbolAddress((void**)&Q,  g_Q);
    cudaGetSymbolAddress((void**)&K,  g_K);
    cudaGetSymbolAddress((void**)&V,  g_V);
    cudaGetSymbolAddress((void**)&Y,  g_Y);
    cudaGetSymbolAddress((void**)&al, g_alpha);
    cudaGetSymbolAddress((void**)&be, g_beta);
    cudaGetSymbolAddress((void**)&U,  g_U);
    cudaGetSymbolAddress((void**)&Sc, g_Sc);
    cudaGetSymbolAddress((void**)&G,  g_G);
    cudaGetSymbolAddress((void**)&gt, g_gt);
    cudaGetSymbolAddress((void**)&xh, g_xh);
    cudaGetSymbolAddress((void**)&xl, g_xl);
    cudaGetSymbolAddress((void**)&yh, g_yh);
    cudaGetSymbolAddress((void**)&yl, g_yl);
    cudaGetSymbolAddress((void**)&wqh, g_wqh); cudaGetSymbolAddress((void**)&wql, g_wql);
    cudaGetSymbolAddress((void**)&wkh, g_wkh); cudaGetSymbolAddress((void**)&wkl, g_wkl);
    cudaGetSymbolAddress((void**)&wvh, g_wvh); cudaGetSymbolAddress((void**)&wvl, g_wvl);
    cudaGetSymbolAddress((void**)&woh, g_woh); cudaGetSymbolAddress((void**)&wol, g_wol);

    cudaFuncSetAttribute(gemm_mma,    cudaFuncAttributeMaxDynamicSharedMemorySize, GEMM_SMEM);
    cudaFuncSetAttribute(chunk_intra, cudaFuncAttributeMaxDynamicSharedMemorySize, 12672*4);

    // conversions
    conv_split<<<ROWS * DMx / 1024, 256>>>(x, xh, xl);
    trans_split<<<dim3(32,32), 256>>>(Wq, wqh, wql);
    trans_split<<<dim3(32,32), 256>>>(Wk, wkh, wkl);
    trans_split<<<dim3(32,32), 256>>>(Wv, wvh, wvl);
    trans_split<<<dim3(32,32), 256>>>(Wo, woh, wol);
    ab_kernel<<<ROWS / 32, 256>>>(x, Wa, ba, Wb, bb, al, be);

    // projections (tensor cores via mma.sync)
    dim3 gproj(INNERx / 128, ROWS / 128);   // (8, 64)
    gemm_mma<<<gproj, 256, GEMM_SMEM>>>(xh, xl, wqh, wql, Q, INNERx);
    gemm_mma<<<gproj, 256, GEMM_SMEM>>>(xh, xl, wkh, wkl, K, INNERx);
    gemm_mma<<<gproj, 256, GEMM_SMEM>>>(xh, xl, wvh, wvl, V, INNERx);

    // chunked linear-attention scan (chunk_inter also emits bf16 split of Y)
    chunk_intra<<<dim3(NCH, BH), 256, 12672*4>>>(Q, K, V, al, be, Y, U, G, gt);
    chunk_scan<<<BH, 256>>>(U, G, state, Sc, stateOut);
    chunk_inter<<<dim3(NCH, BH), 256>>>(Q, Sc, gt, Y, yh, yl);

    // output projection
    dim3 gout(DMx / 128, ROWS / 128);
    gemm_mma<<<gout, 256, GEMM_SMEM>>>(yh, yl, woh, wol, out, DMx);
}

// round 6
// speedup vs baseline: 4.2828x; 1.0477x over previous
#include <cuda_runtime.h>
#include <cuda_bf16.h>
#include <math.h>
#include <cstdint>

#define Bsz 4
#define Tsz 2048
#define DMx 1024
#define Hh  16
#define Dd  64
#define INNERx 1024
#define ROWS (Bsz*Tsz)   // 8192
#define CH 64
#define NCH (Tsz/CH)     // 32
#define BH (Bsz*Hh)      // 64
#define KDIM 1024
#define NCHUNKS 48       // 3*KDIM/64 (3-term split, K-chunk 64)

typedef unsigned long long ull;
typedef __nv_bfloat16 bf16;

// ---------------- scratch ----------------
__device__ float g_Q[ROWS*INNERx];
__device__ float g_K[ROWS*INNERx];
__device__ float g_V[ROWS*INNERx];
__device__ float g_Y[ROWS*INNERx];
__device__ float g_alpha[ROWS*Hh];
__device__ float g_beta[ROWS*Hh];
__device__ float g_U[BH*NCH*Dd*Dd];
__device__ float g_Sc[BH*NCH*Dd*Dd];
__device__ float g_G[BH*NCH];
__device__ float g_gt[BH*Tsz];
__device__ bf16 g_xh[ROWS*DMx];
__device__ bf16 g_xl[ROWS*DMx];
__device__ bf16 g_yh[ROWS*INNERx];
__device__ bf16 g_yl[ROWS*INNERx];
__device__ bf16 g_wqh[DMx*INNERx], g_wql[DMx*INNERx];
__device__ bf16 g_wkh[DMx*INNERx], g_wkl[DMx*INNERx];
__device__ bf16 g_wvh[DMx*INNERx], g_wvl[DMx*INNERx];
__device__ bf16 g_woh[INNERx*DMx], g_wol[INNERx*DMx];

// ---------------- helpers ----------------
__device__ __forceinline__ uint32_t smem_to_u32(const void* p){
    uint32_t a;
    asm("{ .reg .u64 t; cvta.to.shared.u64 t, %1; cvt.u32.u64 %0, t; }" : "=r"(a) : "l"(p));
    return a;
}
__device__ __forceinline__ void cp_async16(uint32_t dst, const void* src){
    asm volatile("cp.async.cg.shared.global [%0], [%1], 16;" :: "r"(dst), "l"(src));
}
#define CP_COMMIT() asm volatile("cp.async.commit_group;" ::: "memory")
#define CP_WAIT(n)  asm volatile("cp.async.wait_group %0;" :: "n"(n) : "memory")

__device__ __forceinline__ void ldsm_x4(uint32_t* r, uint32_t addr){
    asm volatile("ldmatrix.sync.aligned.m8n8.x4.shared.b16 {%0,%1,%2,%3}, [%4];"
        : "=r"(r[0]), "=r"(r[1]), "=r"(r[2]), "=r"(r[3]) : "r"(addr));
}
__device__ __forceinline__ void mma_bf16(float* c, const uint32_t* a, const uint32_t* b){
    asm volatile(
        "mma.sync.aligned.m16n8k16.row.col.f32.bf16.bf16.f32 "
        "{%0,%1,%2,%3}, {%4,%5,%6,%7}, {%8,%9}, {%0,%1,%2,%3};"
        : "+f"(c[0]), "+f"(c[1]), "+f"(c[2]), "+f"(c[3])
        : "r"(a[0]), "r"(a[1]), "r"(a[2]), "r"(a[3]), "r"(b[0]), "r"(b[1]));
}
__device__ __forceinline__ ull pack_dup(float a){
    ull r; unsigned int u = __float_as_uint(a);
    asm("mov.b64 %0, {%1, %1};" : "=l"(r) : "r"(u));
    return r;
}
__device__ __forceinline__ void ffma2(ull& d, ull a, ull b){
    asm("fma.rn.f32x2 %0, %1, %2, %3;" : "=l"(d) : "l"(a), "l"(b), "l"(d));
}
__device__ __forceinline__ float lo_of(ull v){ return __uint_as_float((unsigned)(v & 0xffffffffull)); }
__device__ __forceinline__ float hi_of(ull v){ return __uint_as_float((unsigned)(v >> 32)); }

// ---------------- conversion kernels ----------------
__global__ __launch_bounds__(256)
void conv_split(const float* __restrict__ src, bf16* __restrict__ h,
                bf16* __restrict__ l){
    const size_t i = (size_t)blockIdx.x * 256 + threadIdx.x;
    float4 v = *(const float4*)(src + i * 4);
    bf16 h0 = __float2bfloat16(v.x), h1 = __float2bfloat16(v.y);
    bf16 h2 = __float2bfloat16(v.z), h3 = __float2bfloat16(v.w);
    bf16 l0 = __float2bfloat16(v.x - __bfloat162float(h0));
    bf16 l1 = __float2bfloat16(v.y - __bfloat162float(h1));
    bf16 l2 = __float2bfloat16(v.z - __bfloat162float(h2));
    bf16 l3 = __float2bfloat16(v.w - __bfloat162float(h3));
    __nv_bfloat162* hp = (__nv_bfloat162*)(h + i * 4);
    __nv_bfloat162* lp = (__nv_bfloat162*)(l + i * 4);
    hp[0] = __nv_bfloat162{h0, h1}; hp[1] = __nv_bfloat162{h2, h3};
    lp[0] = __nv_bfloat162{l0, l1}; lp[1] = __nv_bfloat162{l2, l3};
}

// W[K][N] (1024x1024) -> T[N][K] split hi/lo
__global__ __launch_bounds__(256)
void trans_split(const float* __restrict__ W, bf16* __restrict__ Th,
                 bf16* __restrict__ Tl){
    __shared__ float ts[32][33];
    const int k0 = blockIdx.y * 32, n0 = blockIdx.x * 32;
    const int tx = threadIdx.x & 31, ty = threadIdx.x >> 5;
    for (int i = ty; i < 32; i += 8)
        ts[i][tx] = W[(size_t)(k0 + i) * 1024 + n0 + tx];
    __syncthreads();
    for (int i = ty; i < 32; i += 8){
        float v = ts[tx][i];
        bf16 h = __float2bfloat16(v);
        bf16 l = __float2bfloat16(v - __bfloat162float(h));
        Th[(size_t)(n0 + i) * 1024 + k0 + tx] = h;
        Tl[(size_t)(n0 + i) * 1024 + k0 + tx] = l;
    }
}

// ---------------- bf16-split mma.sync GEMM core --------------------------------
// 128x128 CTA tile, 8 warps (2x4) of 64x32, K-chunk 64, 3-stage cp.async,
// single __syncthreads per chunk. Extended K = 3072 via 3 phases.
#define STAGE_BYTES 32768          // A 16KB + B 16KB per stage
#define GEMM_SMEM   (3*STAGE_BYTES)

__device__ __forceinline__ void gemm_core(
    const bf16* __restrict__ Ah, const bf16* __restrict__ Al,
    const bf16* __restrict__ Bh, const bf16* __restrict__ Bl,
    float* __restrict__ C, int N, int bm, int bn)
{
    extern __shared__ __align__(128) char sm[];
    const uint32_t sb = smem_to_u32(sm);
    const int tid = threadIdx.x, lane = tid & 31, wid = tid >> 5;
    const int wm = wid >> 2, wn = wid & 3;

    float acc[4][4][4];
    #pragma unroll
    for (int mt = 0; mt < 4; mt++)
        #pragma unroll
        for (int nt = 0; nt < 4; nt++)
            #pragma unroll
            for (int e = 0; e < 4; e++) acc[mt][nt][e] = 0.f;

    const int urow = tid >> 3, uu = tid & 7;
    const int ubo = urow * 128 + uu * 16;
    const uint32_t uph = ubo ^ ((ubo >> 3) & 0x70);

    auto issue_stage = [&](int buf, int c){
        const int p = c >> 4, kk0 = (c & 15) << 6;
        const bf16* As = (p == 1) ? Al : Ah;
        const bf16* Bs = (p == 2) ? Bl : Bh;
        const uint32_t abase = sb + buf * STAGE_BYTES;
        const uint32_t bbase = abase + 16384;
        #pragma unroll
        for (int i = 0; i < 4; i++){
            const int row = urow + i * 32;
            const uint32_t dph = uph + i * 4096;
            cp_async16(abase + dph, As + (size_t)(bm + row) * KDIM + kk0 + uu * 8);
            cp_async16(bbase + dph, Bs + (size_t)(bn + row) * KDIM + kk0 + uu * 8);
        }
    };

    issue_stage(0, 0); CP_COMMIT();
    issue_stage(1, 1); CP_COMMIT();
    int buf = 0;
    for (int c = 0; c < NCHUNKS; c++){
        if (c >= NCHUNKS - 2) { CP_WAIT(0); } else { CP_WAIT(1); }
        __syncthreads();
        if (c + 2 < NCHUNKS){
            int nb = buf + 2; if (nb >= 3) nb -= 3;
            issue_stage(nb, c + 2); CP_COMMIT();
        }
        const uint32_t abase = sb + buf * STAGE_BYTES;
        const uint32_t bbase = abase + 16384;
        #pragma unroll
        for (int ks = 0; ks < 4; ks++){
            uint32_t afr[4][4];
            #pragma unroll
            for (int mt = 0; mt < 4; mt++){
                const int row = wm * 64 + mt * 16 + (lane & 15);
                const int bo = row * 128 + ks * 32 + ((lane >> 4) << 4);
                ldsm_x4(afr[mt], abase + (bo ^ ((bo >> 3) & 0x70)));
            }
            uint32_t bfr[2][4];
            #pragma unroll
            for (int np = 0; np < 2; np++){
                const int g = lane >> 3;
                const int row = wn * 32 + np * 16 + ((g >> 1) << 3) + (lane & 7);
                const int bo = row * 128 + ks * 32 + ((g & 1) << 4);
                ldsm_x4(bfr[np], bbase + (bo ^ ((bo >> 3) & 0x70)));
            }
            #pragma unroll
            for (int mt = 0; mt < 4; mt++)
                #pragma unroll
                for (int nt = 0; nt < 4; nt++)
                    mma_bf16(acc[mt][nt], afr[mt], &bfr[nt >> 1][(nt & 1) * 2]);
        }
        buf++; if (buf >= 3) buf = 0;
    }

    const int r0 = lane >> 2, cb = (lane & 3) << 1;
    #pragma unroll
    for (int mt = 0; mt < 4; mt++){
        const int grow = bm + wm * 64 + mt * 16 + r0;
        #pragma unroll
        for (int nt = 0; nt < 4; nt++){
            const int gcol = bn + wn * 32 + nt * 8 + cb;
            *(float2*)(C + (size_t)grow * N + gcol) =
                make_float2(acc[mt][nt][0], acc[mt][nt][1]);
            *(float2*)(C + (size_t)(grow + 8) * N + gcol) =
                make_float2(acc[mt][nt][2], acc[mt][nt][3]);
        }
    }
}

// fused Q/K/V projection: grid (24, 64); column tile selects weight + output
__global__ __launch_bounds__(256, 2)
void gemm_qkv(const bf16* __restrict__ Ah, const bf16* __restrict__ Al,
              const bf16* __restrict__ Wqh, const bf16* __restrict__ Wql,
              const bf16* __restrict__ Wkh, const bf16* __restrict__ Wkl,
              const bf16* __restrict__ Wvh, const bf16* __restrict__ Wvl,
              float* __restrict__ Q, float* __restrict__ K, float* __restrict__ V){
    const int sel = blockIdx.x >> 3;
    const int bn = (blockIdx.x & 7) * 128;
    const int bm = blockIdx.y * 128;
    const bf16* Bh = (sel == 0) ? Wqh : (sel == 1) ? Wkh : Wvh;
    const bf16* Bl = (sel == 0) ? Wql : (sel == 1) ? Wkl : Wvl;
    float* C = (sel == 0) ? Q : (sel == 1) ? K : V;
    gemm_core(Ah, Al, Bh, Bl, C, INNERx, bm, bn);
}

__global__ __launch_bounds__(256, 2)
void gemm_mma(const bf16* __restrict__ Ah, const bf16* __restrict__ Al,
              const bf16* __restrict__ Bh, const bf16* __restrict__ Bl,
              float* __restrict__ C, int N){
    gemm_core(Ah, Al, Bh, Bl, C, N, blockIdx.y * 128, blockIdx.x * 128);
}

// ---------------- alpha/beta gate GEMM ----------------
__global__ __launch_bounds__(256)
void ab_kernel(const float* __restrict__ x,
               const float* __restrict__ Wa, const float* __restrict__ ba,
               const float* __restrict__ Wb, const float* __restrict__ bb,
               float* __restrict__ alpha, float* __restrict__ beta){
    __shared__ float xs[32][40];
    __shared__ float Ws[32][32];
    const int tid = threadIdx.x;
    const int r = tid >> 3, sub = tid & 7;
    const int row0 = blockIdx.x * 32;
    ull acc[2] = {0ull, 0ull};
    for (int k0 = 0; k0 < DMx; k0 += 32){
        #pragma unroll
        for (int q = 0; q < 4; q++){
            int idx = tid + q * 256;
            int kk = idx >> 5, cc = idx & 31;
            Ws[kk][cc] = (cc < 16) ? Wa[(size_t)(k0 + kk) * Hh + cc]
                                   : Wb[(size_t)(k0 + kk) * Hh + cc - 16];
        }
        {
            const int rr = tid >> 3, seg = tid & 7;
            float4 v = *(const float4*)(x + (size_t)(row0 + rr) * DMx + k0 + seg * 4);
            *(float4*)&xs[rr][seg * 4] = v;
        }
        __syncthreads();
        #pragma unroll
        for (int kk = 0; kk < 32; kk++){
            ull xv = pack_dup(xs[r][kk]);
            const ull* wp = (const ull*)&Ws[kk][sub * 4];
            ffma2(acc[0], xv, wp[0]);
            ffma2(acc[1], xv, wp[1]);
        }
        __syncthreads();
    }
    #pragma unroll
    for (int j = 0; j < 2; j++){
        float lo = lo_of(acc[j]), hi = hi_of(acc[j]);
        #pragma unroll
        for (int p = 0; p < 2; p++){
            float v = p ? hi : lo;
            int cc = sub * 4 + j * 2 + p;
            float bias = (cc < 16) ? ba[cc] : bb[cc - 16];
            float sig = 1.f / (1.f + expf(-(v + bias)));
            if (cc < 16) alpha[(size_t)(row0 + r) * Hh + cc] = sig;
            else         beta [(size_t)(row0 + r) * Hh + cc - 16] = sig;
        }
    }
}

// ---------------- K1: intra-chunk attention + chunk summary --------------------
// smem tiles padded to 66 floats/row so float2 (LDS.64) accesses stay aligned.
#define TP 66
#define INTRA_SMEM ((3*64*TP + 192) * 4)

__global__ __launch_bounds__(256)
void chunk_intra(const float* __restrict__ Q, const float* __restrict__ K,
                 const float* __restrict__ V,
                 const float* __restrict__ alpha, const float* __restrict__ beta,
                 float* __restrict__ Yout, float* __restrict__ U,
                 float* __restrict__ Gout, float* __restrict__ gt_out){
    extern __shared__ float smf[];
    float* Qs  = smf;                 // 64*TP, later reused as P
    float* Ks  = smf + 64*TP;
    float* Vs  = smf + 2*64*TP;
    float* slg = smf + 3*64*TP;
    float* sb  = slg + 64;
    float* sw  = sb + 64;

    const int c  = blockIdx.x;
    const int bh = blockIdx.y;
    const int b  = bh >> 4, h = bh & 15;
    const int tid = threadIdx.x;
    const size_t base = ((size_t)(b * Tsz + c * CH) * Hh + h) * Dd;

    {
        const int r = tid >> 2, quad = tid & 3;
        const size_t off = base + (size_t)r * INNERx + quad * 16;
        float4 q0 = *(const float4*)(Q + off),     q1 = *(const float4*)(Q + off + 4);
        float4 q2 = *(const float4*)(Q + off + 8), q3 = *(const float4*)(Q + off + 12);
        float4 k0 = *(const float4*)(K + off),     k1 = *(const float4*)(K + off + 4);
        float4 k2 = *(const float4*)(K + off + 8), k3 = *(const float4*)(K + off + 12);
        float4 v0 = *(const float4*)(V + off),     v1 = *(const float4*)(V + off + 4);
        float4 v2 = *(const float4*)(V + off + 8), v3 = *(const float4*)(V + off + 12);
        float ss = k0.x*k0.x + k0.y*k0.y + k0.z*k0.z + k0.w*k0.w
                 + k1.x*k1.x + k1.y*k1.y + k1.z*k1.z + k1.w*k1.w
                 + k2.x*k2.x + k2.y*k2.y + k2.z*k2.z + k2.w*k2.w
                 + k3.x*k3.x + k3.y*k3.y + k3.z*k3.z + k3.w*k3.w;
        ss += __shfl_xor_sync(0xffffffffu, ss, 1);
        ss += __shfl_xor_sync(0xffffffffu, ss, 2);
        float inv = 1.f / fmaxf(sqrtf(ss), 1e-12f);
        float* qr = Qs + r * TP + quad * 16;
        float* kr = Ks + r * TP + quad * 16;
        float* vr = Vs + r * TP + quad * 16;
        qr[0]=q0.x; qr[1]=q0.y; qr[2]=q0.z; qr[3]=q0.w;
        qr[4]=q1.x; qr[5]=q1.y; qr[6]=q1.z; qr[7]=q1.w;
        qr[8]=q2.x; qr[9]=q2.y; qr[10]=q2.z; qr[11]=q2.w;
        qr[12]=q3.x; qr[13]=q3.y; qr[14]=q3.z; qr[15]=q3.w;
        kr[0]=k0.x*inv; kr[1]=k0.y*inv; kr[2]=k0.z*inv; kr[3]=k0.w*inv;
        kr[4]=k1.x*inv; kr[5]=k1.y*inv; kr[6]=k1.z*inv; kr[7]=k1.w*inv;
        kr[8]=k2.x*inv; kr[9]=k2.y*inv; kr[10]=k2.z*inv; kr[11]=k2.w*inv;
        kr[12]=k3.x*inv; kr[13]=k3.y*inv; kr[14]=k3.z*inv; kr[15]=k3.w*inv;
        vr[0]=v0.x; vr[1]=v0.y; vr[2]=v0.z; vr[3]=v0.w;
        vr[4]=v1.x; vr[5]=v1.y; vr[6]=v1.z; vr[7]=v1.w;
        vr[8]=v2.x; vr[9]=v2.y; vr[10]=v2.z; vr[11]=v2.w;
        vr[12]=v3.x; vr[13]=v3.y; vr[14]=v3.z; vr[15]=v3.w;
    }
    if (tid < 64){
        size_t gidx = (size_t)(b * Tsz + c * CH + tid) * Hh + h;
        slg[tid] = __logf(alpha[gidx]);
        sb[tid]  = beta[gidx];
    }
    __syncthreads();
    if (tid == 0){
        float s = 0.f;
        for (int j = 0; j < CH; j++){ s += slg[j]; slg[j] = s; }
    }
    __syncthreads();
    if (tid < 64){
        float lg_last = slg[63];
        sw[tid] = __expf(lg_last - slg[tid]) * sb[tid];
        float g = __expf(slg[tid]);
        gt_out[(size_t)bh * Tsz + c * CH + tid] = g;
        if (tid == 63) Gout[bh * NCH + c] = g;
    }
    __syncthreads();

    const int tr  = (tid >> 4) << 2;
    const int tc4 = (tid & 15) << 2;

    // phase M: M[tau][j] = q_tau . k_j  (packed pairs over d)
    ull accM2[4][4];
    #pragma unroll
    for (int i=0;i<4;i++)
        #pragma unroll
        for (int j=0;j<4;j++) accM2[i][j] = 0ull;
    #pragma unroll 8
    for (int d = 0; d < Dd; d += 2){
        ull q2[4], k2[4];
        #pragma unroll
        for (int i=0;i<4;i++) q2[i] = *(const ull*)&Qs[(tr+i)*TP + d];
        #pragma unroll
        for (int j=0;j<4;j++) k2[j] = *(const ull*)&Ks[(tc4+j)*TP + d];
        #pragma unroll
        for (int i=0;i<4;i++)
            #pragma unroll
            for (int j=0;j<4;j++) ffma2(accM2[i][j], q2[i], k2[j]);
    }
    __syncthreads();   // all reads of Qs done
    #pragma unroll
    for (int i=0;i<4;i++){
        int tau = tr + i;
        float lgt = slg[tau];
        #pragma unroll
        for (int j=0;j<4;j++){
            int jj = tc4 + j;
            float p = 0.f;
            if (tau >= jj)
                p = __expf(lgt - slg[jj]) * sb[jj] * (lo_of(accM2[i][j]) + hi_of(accM2[i][j]));
            Qs[tau*TP + jj] = p;
        }
    }
    __syncthreads();

    // phase Y: Yintra = P @ V ; phase U: U = V^T diag(w) K  (packed pairs over d-cols)
    ull accY2[4][2], accU2[4][2];
    #pragma unroll
    for (int i=0;i<4;i++){
        accY2[i][0]=0ull; accY2[i][1]=0ull; accU2[i][0]=0ull; accU2[i][1]=0ull;
    }
    #pragma unroll 4
    for (int j = 0; j < CH; j++){
        float wj = sw[j];
        ull vf0 = *(const ull*)&Vs[j*TP + tc4];
        ull vf1 = *(const ull*)&Vs[j*TP + tc4 + 2];
        ull kf0 = *(const ull*)&Ks[j*TP + tc4];
        ull kf1 = *(const ull*)&Ks[j*TP + tc4 + 2];
        #pragma unroll
        for (int i=0;i<4;i++){
            ull pf = pack_dup(Qs[(tr+i)*TP + j]);
            ull vu = pack_dup(Vs[j*TP + tr + i] * wj);
            ffma2(accY2[i][0], pf, vf0);
            ffma2(accY2[i][1], pf, vf1);
            ffma2(accU2[i][0], vu, kf0);
            ffma2(accU2[i][1], vu, kf1);
        }
    }
    #pragma unroll
    for (int i=0;i<4;i++){
        float* yr = Yout + base + (size_t)(tr + i) * INNERx + tc4;
        *(float4*)yr = make_float4(lo_of(accY2[i][0]), hi_of(accY2[i][0]),
                                   lo_of(accY2[i][1]), hi_of(accY2[i][1]));
        float* ur = U + ((size_t)(bh * NCH + c) * 4096) + (tr + i) * 64 + tc4;
        *(float4*)ur = make_float4(lo_of(accU2[i][0]), hi_of(accU2[i][0]),
                                   lo_of(accU2[i][1]), hi_of(accU2[i][1]));
    }
}

// ---------------- K2: chunk-level state scan -----------------------------------
__global__ __launch_bounds__(256)
void chunk_scan(const float* __restrict__ U, const float* __restrict__ G,
                const float* __restrict__ state0,
                float* __restrict__ Sc, float* __restrict__ stateOut){
    const int bh = blockIdx.x;
    const int tid = threadIdx.x;
    float S[16];
    const size_t bs = (size_t)bh * 4096;
    #pragma unroll
    for (int j = 0; j < 16; j++) S[j] = state0[bs + j * 256 + tid];
    for (int c = 0; c < NCH; c++){
        const size_t uc = ((size_t)(bh * NCH + c)) * 4096;
        float g = __ldg(&G[bh * NCH + c]);
        float u[16];
        #pragma unroll
        for (int j = 0; j < 16; j++) u[j] = U[uc + j * 256 + tid];
        #pragma unroll
        for (int j = 0; j < 16; j++){
            Sc[uc + j * 256 + tid] = S[j];
            S[j] = fmaf(g, S[j], u[j]);
        }
    }
    #pragma unroll
    for (int j = 0; j < 16; j++) stateOut[bs + j * 256 + tid] = S[j];
}

// ---------------- K3: Y += diag(g) Q S^T ; emit bf16 hi/lo split of Y ----------
__global__ __launch_bounds__(256)
void chunk_inter(const float* __restrict__ Q, const float* __restrict__ Sc,
                 const float* __restrict__ gt, const float* __restrict__ Y,
                 bf16* __restrict__ Yh, bf16* __restrict__ Yl){
    __shared__ float Qs[64*TP];
    __shared__ float Ss[64*TP];
    __shared__ float sg[64];
    const int c  = blockIdx.x;
    const int bh = blockIdx.y;
    const int b  = bh >> 4, h = bh & 15;
    const int tid = threadIdx.x;
    const size_t base = ((size_t)(b * Tsz + c * CH) * Hh + h) * Dd;
    {
        const int r = tid >> 2, quad = tid & 3;
        const size_t off = base + (size_t)r * INNERx + quad * 16;
        const size_t soff = ((size_t)(bh * NCH + c)) * 4096 + r * 64 + quad * 16;
        #pragma unroll
        for (int l = 0; l < 16; l += 4){
            float4 qv = *(const float4*)(Q + off + l);
            float4 sv = *(const float4*)(Sc + soff + l);
            float* qr = Qs + r * TP + quad * 16 + l;
            float* sr = Ss + r * TP + quad * 16 + l;
            qr[0]=qv.x; qr[1]=qv.y; qr[2]=qv.z; qr[3]=qv.w;
            sr[0]=sv.x; sr[1]=sv.y; sr[2]=sv.z; sr[3]=sv.w;
        }
    }
    if (tid < 64) sg[tid] = gt[(size_t)bh * Tsz + c * CH + tid];
    __syncthreads();
    const int tr  = (tid >> 4) << 2;   // tau rows
    const int tci = (tid & 15) << 2;   // v-dim cols
    ull acc2[4][4];
    #pragma unroll
    for (int i=0;i<4;i++)
        #pragma unroll
        for (int k=0;k<4;k++) acc2[i][k] = 0ull;
    #pragma unroll 8
    for (int j = 0; j < Dd; j += 2){
        ull qf2[4], sf2[4];
        #pragma unroll
        for (int i=0;i<4;i++) qf2[i] = *(const ull*)&Qs[(tr+i)*TP + j];
        #pragma unroll
        for (int k=0;k<4;k++) sf2[k] = *(const ull*)&Ss[(tci+k)*TP + j];
        #pragma unroll
        for (int i=0;i<4;i++)
            #pragma unroll
            for (int k=0;k<4;k++) ffma2(acc2[i][k], qf2[i], sf2[k]);
    }
    #pragma unroll
    for (int i=0;i<4;i++){
        float gt_ = sg[tr + i];
        const size_t off = base + (size_t)(tr + i) * INNERx + tci;
        float4 old = *(const float4*)(Y + off);
        float f0 = fmaf(gt_, lo_of(acc2[i][0]) + hi_of(acc2[i][0]), old.x);
        float f1 = fmaf(gt_, lo_of(acc2[i][1]) + hi_of(acc2[i][1]), old.y);
        float f2 = fmaf(gt_, lo_of(acc2[i][2]) + hi_of(acc2[i][2]), old.z);
        float f3 = fmaf(gt_, lo_of(acc2[i][3]) + hi_of(acc2[i][3]), old.w);
        bf16 h0 = __float2bfloat16(f0), h1 = __float2bfloat16(f1);
        bf16 h2 = __float2bfloat16(f2), h3 = __float2bfloat16(f3);
        bf16 l0 = __float2bfloat16(f0 - __bfloat162float(h0));
        bf16 l1 = __float2bfloat16(f1 - __bfloat162float(h1));
        bf16 l2 = __float2bfloat16(f2 - __bfloat162float(h2));
        bf16 l3 = __float2bfloat16(f3 - __bfloat162float(h3));
        __nv_bfloat162* hp = (__nv_bfloat162*)(Yh + off);
        __nv_bfloat162* lp = (__nv_bfloat162*)(Yl + off);
        hp[0] = __nv_bfloat162{h0, h1}; hp[1] = __nv_bfloat162{h2, h3};
        lp[0] = __nv_bfloat162{l0, l1}; lp[1] = __nv_bfloat162{l2, l3};
    }
}

// ---------------- launcher -----------------------------------------------------
extern "C" void kernel_launch(void* const* d_in, const int* in_sizes, int n_in,
                              void* d_out, int out_size){
    const float* x     = (const float*)d_in[0];
    const float* state = (const float*)d_in[1];
    const float* Wq    = (const float*)d_in[2];
    const float* Wk    = (const float*)d_in[3];
    const float* Wv    = (const float*)d_in[4];
    const float* Wa    = (const float*)d_in[5];
    const float* ba    = (const float*)d_in[6];
    const float* Wb    = (const float*)d_in[7];
    const float* bb    = (const float*)d_in[8];
    const float* Wo    = (const float*)d_in[9];

    float* out      = (float*)d_out;
    float* stateOut = out + (size_t)ROWS * DMx;

    float *Q, *K, *V, *Y, *al, *be, *U, *Sc, *G, *gt;
    bf16 *xh, *xl, *yh, *yl, *wqh, *wql, *wkh, *wkl, *wvh, *wvl, *woh, *wol;
    cudaGetSymbolAddress((void**)&Q,  g_Q);
    cudaGetSymbolAddress((void**)&K,  g_K);
    cudaGetSymbolAddress((void**)&V,  g_V);
    cudaGetSymbolAddress((void**)&Y,  g_Y);
    cudaGetSymbolAddress((void**)&al, g_alpha);
    cudaGetSymbolAddress((void**)&be, g_beta);
    cudaGetSymbolAddress((void**)&U,  g_U);
    cudaGetSymbolAddress((void**)&Sc, g_Sc);
    cudaGetSymbolAddress((void**)&G,  g_G);
    cudaGetSymbolAddress((void**)&gt, g_gt);
    cudaGetSymbolAddress((void**)&xh, g_xh);
    cudaGetSymbolAddress((void**)&xl, g_xl);
    cudaGetSymbolAddress((void**)&yh, g_yh);
    cudaGetSymbolAddress((void**)&yl, g_yl);
    cudaGetSymbolAddress((void**)&wqh, g_wqh); cudaGetSymbolAddress((void**)&wql, g_wql);
    cudaGetSymbolAddress((void**)&wkh, g_wkh); cudaGetSymbolAddress((void**)&wkl, g_wkl);
    cudaGetSymbolAddress((void**)&wvh, g_wvh); cudaGetSymbolAddress((void**)&wvl, g_wvl);
    cudaGetSymbolAddress((void**)&woh, g_woh); cudaGetSymbolAddress((void**)&wol, g_wol);

    cudaFuncSetAttribute(gemm_qkv,    cudaFuncAttributeMaxDynamicSharedMemorySize, GEMM_SMEM);
    cudaFuncSetAttribute(gemm_mma,    cudaFuncAttributeMaxDynamicSharedMemorySize, GEMM_SMEM);
    cudaFuncSetAttribute(chunk_intra, cudaFuncAttributeMaxDynamicSharedMemorySize, INTRA_SMEM);

    // conversions
    conv_split<<<ROWS * DMx / 1024, 256>>>(x, xh, xl);
    trans_split<<<dim3(32,32), 256>>>(Wq, wqh, wql);
    trans_split<<<dim3(32,32), 256>>>(Wk, wkh, wkl);
    trans_split<<<dim3(32,32), 256>>>(Wv, wvh, wvl);
    trans_split<<<dim3(32,32), 256>>>(Wo, woh, wol);
    ab_kernel<<<ROWS / 32, 256>>>(x, Wa, ba, Wb, bb, al, be);

    // fused Q/K/V projections (tensor cores via mma.sync)
    gemm_qkv<<<dim3(24, ROWS / 128), 256, GEMM_SMEM>>>(
        xh, xl, wqh, wql, wkh, wkl, wvh, wvl, Q, K, V);

    // chunked linear-attention scan (chunk_inter also emits bf16 split of Y)
    chunk_intra<<<dim3(NCH, BH), 256, INTRA_SMEM>>>(Q, K, V, al, be, Y, U, G, gt);
    chunk_scan<<<BH, 256>>>(U, G, state, Sc, stateOut);
    chunk_inter<<<dim3(NCH, BH), 256>>>(Q, Sc, gt, Y, yh, yl);

    // output projection
    dim3 gout(DMx / 128, ROWS / 128);
    gemm_mma<<<gout, 256, GEMM_SMEM>>>(yh, yl, woh, wol, out, DMx);
}